// round 15
// baseline (speedup 1.0000x reference)
#include <cuda_runtime.h>
#include <cuda_fp16.h>
#include <cstdint>

// Problem dims (fixed per reference setup_inputs)
#define BB 8
#define SS 2048
#define DD 512
#define II 2048
#define MM (BB*SS)   // 16384 rows (b*S+s)
#define NN (2*II)    // 4096 interleaved output cols (even=pa, odd=pi)

#define LN3 1.0986122886681098f

// GEMM tiling
#define CTA_M 128
#define CTA_N 128          // = 64 channels
#define TK 64              // K halves per chunk (128B rows)
#define NCHUNK (DD/TK)     // 8
#define STAGES 3
#define STAGE_BYTES 32768  // x 16K + Wcat 16K
#define W_OFF 16384

#define NCOLS (NN / CTA_N)     // 32
#define NMB   (MM / CTA_M)     // 128
#define TILE_STRIDE 65         // half2 per row (padded: conflict-free)

// Scratch
__device__ __half g_xh[(size_t)MM * DD];    // [m, k]
__device__ __half g_wc[(size_t)NN * DD];    // interleaved [2i+p, k]
__device__ float  g_carry[(size_t)II * BB]; // h carry per (channel, b)
__device__ int    g_flag[NCOLS * NMB];      // segment-done flags

__device__ __forceinline__ uint32_t s2u(const void* p) {
    uint32_t a;
    asm("{ .reg .u64 t; cvta.to.shared.u64 t, %1; cvt.u32.u64 %0, t; }" : "=r"(a) : "l"(p));
    return a;
}

__device__ __forceinline__ uint32_t h2u(__half2 h) {
    uint32_t u;
    memcpy(&u, &h, 4);
    return u;
}

// SW128-style swizzle for 128-byte rows (64 halves)
__device__ __forceinline__ uint32_t swz(uint32_t o) { return o ^ ((o >> 3) & 0x70); }

__device__ __forceinline__ void cpa16(uint32_t dst, const void* src) {
    asm volatile("cp.async.cg.shared.global [%0], [%1], 16;" :: "r"(dst), "l"(src) : "memory");
}
__device__ __forceinline__ void cpa_commit() {
    asm volatile("cp.async.commit_group;" ::: "memory");
}
__device__ __forceinline__ void cpa_wait1() {
    asm volatile("cp.async.wait_group 1;" ::: "memory");
}

__device__ __forceinline__ void ldm_x4(uint32_t* r, uint32_t addr) {
    asm volatile("ldmatrix.sync.aligned.m8n8.x4.shared.b16 {%0,%1,%2,%3}, [%4];"
                 : "=r"(r[0]), "=r"(r[1]), "=r"(r[2]), "=r"(r[3]) : "r"(addr));
}

__device__ __forceinline__ void mma_f16(float* d, const uint32_t* a, uint32_t b0, uint32_t b1) {
    asm volatile(
        "mma.sync.aligned.m16n8k16.row.col.f32.f16.f16.f32 "
        "{%0,%1,%2,%3}, {%4,%5,%6,%7}, {%8,%9}, {%0,%1,%2,%3};\n"
        : "+f"(d[0]), "+f"(d[1]), "+f"(d[2]), "+f"(d[3])
        : "r"(a[0]), "r"(a[1]), "r"(a[2]), "r"(a[3]), "r"(b0), "r"(b1));
}

__device__ __forceinline__ float sigmoidf_(float v) {
    return 1.0f / (1.0f + __expf(-v));
}

// ---- zero per-launch flags (graph replays re-run this) ----
__global__ void zero_flags_kernel()
{
    int i = blockIdx.x * blockDim.x + threadIdx.x;
    if (i < NCOLS * NMB) g_flag[i] = 0;
}

// ---- fp32 -> fp16 convert (x), streaming ----
__global__ void cvt_kernel(const float4* __restrict__ src, __half2* __restrict__ dst, int n4)
{
    int i = blockIdx.x * blockDim.x + threadIdx.x;
    if (i < n4) {
        float4 v = __ldcs(&src[i]);
        uint2 pk = make_uint2(h2u(__floats2half2_rn(v.x, v.y)),
                              h2u(__floats2half2_rn(v.z, v.w)));
        __stcs(reinterpret_cast<uint2*>(dst) + i, pk);
    }
}

// ---- fp32 -> fp16, interleaving W rows: dst row = 2*srcrow + parity ----
__global__ void cvt_w_kernel(const float4* __restrict__ src, int parity, int n4)
{
    int i = blockIdx.x * blockDim.x + threadIdx.x;
    if (i < n4) {
        float4 v = __ldcs(&src[i]);
        int row = i >> 7;              // DD/4 = 128 float4 per row
        int c4  = i & 127;
        uint2 pk = make_uint2(h2u(__floats2half2_rn(v.x, v.y)),
                              h2u(__floats2half2_rn(v.z, v.w)));
        uint2* dst = reinterpret_cast<uint2*>(g_wc) +
                     ((size_t)(2 * row + parity) * (DD / 4) + c4);
        __stcs(dst, pk);
    }
}

// ---- Fused GEMM + gate + carry-chained scan ----
// grid (NCOLS, NMB) = (32, 128): m is the SLOW axis -> CTA bid order matches
// the scan dependency order (predecessor segment always has a lower bid).
// 256 threads (8 warps, 2x4), 2 CTAs/SM.
__global__ void __launch_bounds__(256, 2) fused_kernel(
    const float* __restrict__ ba, const float* __restrict__ bi,
    const float* __restrict__ gate, float* __restrict__ out)
{
    extern __shared__ char smem[];
    const uint32_t sbase = s2u(smem);

    const int tid  = threadIdx.x;
    const int wid  = tid >> 5;
    const int lane = tid & 31;
    const int wm   = wid >> 2;          // 0..1 -> 64-row slice
    const int wn   = wid & 3;           // 0..3 -> 32-col slice
    const int g    = lane >> 2;         // 0..7
    const int tg   = lane & 3;          // 0..3
    const int col  = blockIdx.x;        // 0..31
    const int mb   = blockIdx.y;        // 0..127
    const int m_blk = mb * CTA_M;
    const int n_blk = col * CTA_N;

    float acc[4][4][4];                 // [mt][nt][frag]
    #pragma unroll
    for (int mt = 0; mt < 4; mt++)
        #pragma unroll
        for (int nt = 0; nt < 4; nt++)
            #pragma unroll
            for (int r = 0; r < 4; r++) acc[mt][nt][r] = 0.f;

    // ---- base-register + immediate cp.async addressing ----
    const int r0 = tid >> 3, c0 = tid & 7;
    const uint32_t xs0 = sbase + swz(r0 * 128 + c0 * 16);
    const uint32_t ws0 = sbase + W_OFF + swz(r0 * 128 + c0 * 16);
    const __half* xg0 = g_xh + (size_t)(m_blk + r0) * DD + c0 * 8;
    const __half* wg0 = g_wc + (size_t)(n_blk + r0) * DD + c0 * 8;

    auto issue = [&](int kc, int slot) {   // kc, slot compile-time under unroll
        #pragma unroll
        for (int t = 0; t < 4; t++)
            cpa16(xs0 + slot * STAGE_BYTES + t * 4096,
                  xg0 + kc * TK + t * 32 * DD);
        #pragma unroll
        for (int t = 0; t < 4; t++)
            cpa16(ws0 + slot * STAGE_BYTES + t * 4096,
                  wg0 + kc * TK + t * 32 * DD);
        cpa_commit();
    };

    issue(0, 0); issue(1, 1);

    // Absolute swizzled ldsm offsets. swz(row*128 + kb), kb = kk*32 + acol:
    //   = row*128 + ((acol ^ ((row&7)<<4)) ^ kk*32)   (kk bits never carry)
    const int arow = lane & 15;
    const uint32_t acol = (lane >> 4) << 4;   // 0 or 16
    uint32_t aoff[4], boff[2];
    #pragma unroll
    for (int mt = 0; mt < 4; mt++) {
        int row = wm * 64 + mt * 16 + arow;
        aoff[mt] = sbase + row * 128 + (acol ^ ((row & 7) << 4));
    }
    #pragma unroll
    for (int bt = 0; bt < 2; bt++) {
        int row = wn * 32 + bt * 16 + arow;
        boff[bt] = sbase + W_OFF + row * 128 + (acol ^ ((row & 7) << 4));
    }

    #pragma unroll
    for (int kc = 0; kc < NCHUNK; kc++) {
        cpa_wait1();            // own group kc complete (kc+1 may be in flight)
        __syncthreads();        // ALL threads' waits done -> stage-kc data visible
        if (kc + 2 < NCHUNK) issue(kc + 2, (kc + 2) % STAGES);
        else cpa_commit();      // keep group counting uniform

        const uint32_t so = (kc % STAGES) * STAGE_BYTES;   // immediate under unroll

        // register double-buffered fragments
        uint32_t a[2][4][4], bw[2][2][4];
        #pragma unroll
        for (int mt = 0; mt < 4; mt++) ldm_x4(a[0][mt], aoff[mt] + so);
        #pragma unroll
        for (int bt = 0; bt < 2; bt++) ldm_x4(bw[0][bt], boff[bt] + so);

        #pragma unroll
        for (int kk = 0; kk < 4; kk++) {
            const int cur = kk & 1, nxt = cur ^ 1;
            if (kk < 3) {
                const uint32_t kx = (kk + 1) * 32;
                #pragma unroll
                for (int mt = 0; mt < 4; mt++) ldm_x4(a[nxt][mt], (aoff[mt] + so) ^ kx);
                #pragma unroll
                for (int bt = 0; bt < 2; bt++) ldm_x4(bw[nxt][bt], (boff[bt] + so) ^ kx);
            }
            #pragma unroll
            for (int mt = 0; mt < 4; mt++)
                #pragma unroll
                for (int nt = 0; nt < 4; nt++) {
                    const int bt = nt >> 1, sub = nt & 1;
                    mma_f16(acc[mt][nt], a[cur][mt], bw[cur][bt][sub], bw[cur][bt][sub + 2]);
                }
        }
    }

    // ---- epilogue 1: gate math -> smem tile of half2(alpha, drive) ----
    __syncthreads();   // all warps done with stage smem; safe to overwrite
    __half2* tile = reinterpret_cast<__half2*>(smem);   // [128][TILE_STRIDE]
    #pragma unroll
    for (int nt = 0; nt < 4; nt++) {
        const int ch = wn * 16 + nt * 4 + tg;             // 0..63
        const int i = col * 64 + ch;                      // global channel
        const float bav = __ldg(&ba[i]);
        const float biv = __ldg(&bi[i]);
        const float alv = sigmoidf_(__ldg(&gate[i]));
        #pragma unroll
        for (int mt = 0; mt < 4; mt++) {
            #pragma unroll
            for (int half = 0; half < 2; half++) {
                const int ml = wm * 64 + mt * 16 + g + half * 8;   // 0..127
                float pa = acc[mt][nt][2 * half]     + bav;
                float pi = acc[mt][nt][2 * half + 1] + biv;
                float rg = sigmoidf_(pa);
                float ig = sigmoidf_(pi);
                float aa = alv * __expf(-LN3 * rg);
                float dr = sqrtf(fmaxf(1.0f - aa * aa, 0.0f)) * (ig * pi);
                tile[ml * TILE_STRIDE + ch] = __floats2half2_rn(aa, dr);
            }
        }
    }
    __syncthreads();

    // ---- epilogue 2: carry-chained scan over this CTA's 128 s-steps ----
    const int b   = mb >> 4;       // 16 m-blocks per batch
    const int seg = mb & 15;       // segment index within batch
    if (tid < 64) {
        const int i = col * 64 + tid;
        float h = 0.0f;
        if (seg) {
            volatile int* fp = &g_flag[col * NMB + mb - 1];
            while (*fp == 0) { }
            __threadfence();
            h = g_carry[(size_t)i * BB + b];
        }
        float* op = out + ((size_t)b * SS + seg * 128) * II + i;
        #pragma unroll 4
        for (int s = 0; s < 128; s++) {
            float2 p = __half22float2(tile[s * TILE_STRIDE + tid]);
            h = fmaf(p.x, h, p.y);
            __stcs(&op[(size_t)s * II], h);
        }
        if (seg != 15) g_carry[(size_t)i * BB + b] = h;
    }
    __syncthreads();               // all 64 carries written
    if (tid == 0 && seg != 15) {
        __threadfence();           // carries visible before flag
        atomicExch(&g_flag[col * NMB + mb], 1);
    }
}

extern "C" void kernel_launch(void* const* d_in, const int* in_sizes, int n_in,
                              void* d_out, int out_size)
{
    const float* x    = (const float*)d_in[0];
    const float* Wa   = (const float*)d_in[1];
    const float* ba   = (const float*)d_in[2];
    const float* Wi   = (const float*)d_in[3];
    const float* bi   = (const float*)d_in[4];
    const float* gate = (const float*)d_in[5];
    float* out = (float*)d_out;

    __half* xh; cudaGetSymbolAddress((void**)&xh, g_xh);

    zero_flags_kernel<<<(NCOLS * NMB + 255) / 256, 256>>>();

    const int nx4 = MM * DD / 4;
    const int nw4 = II * DD / 4;
    cvt_kernel<<<(nx4 + 255) / 256, 256>>>((const float4*)x, (__half2*)xh, nx4);
    cvt_w_kernel<<<(nw4 + 255) / 256, 256>>>((const float4*)Wa, 0, nw4);
    cvt_w_kernel<<<(nw4 + 255) / 256, 256>>>((const float4*)Wi, 1, nw4);

    cudaFuncSetAttribute(fused_kernel,
                         cudaFuncAttributeMaxDynamicSharedMemorySize,
                         STAGES * STAGE_BYTES);
    dim3 grid(NCOLS, NMB);   // (32, 128): m slow -> dependency-ordered bids
    fused_kernel<<<grid, 256, STAGES * STAGE_BYTES>>>(ba, bi, gate, out);
}

// round 16
// speedup vs baseline: 1.3863x; 1.3863x over previous
#include <cuda_runtime.h>
#include <cuda_fp16.h>
#include <cstdint>

// Problem dims (fixed per reference setup_inputs)
#define BB 8
#define SS 2048
#define DD 512
#define II 2048
#define MM (BB*SS)   // 16384 rows (b*S+s)
#define NN (2*II)    // 4096 interleaved output cols (even=pa, odd=pi)

#define LN3 1.0986122886681098f

// GEMM tiling
#define CTA_M 128
#define CTA_N 128          // = 64 channels
#define TK 64              // K halves per chunk (128B rows)
#define NCHUNK (DD/TK)     // 8
#define STAGES 3
#define STAGE_BYTES 32768  // x 16K + Wcat 16K
#define W_OFF 16384

#define NCOLS (NN / CTA_N)     // 32
#define NMB   (MM / CTA_M)     // 128
#define NSEG  16               // segments per batch chain
#define TILE_STRIDE 65         // half2 per row (padded: conflict-free)

// Scratch
__device__ __half g_xh[(size_t)MM * DD];    // [m, k]
__device__ __half g_wc[(size_t)NN * DD];    // interleaved [2i+p, k]
__device__ float  g_carry[(size_t)II * BB]; // h carry per (channel, b)
__device__ int    g_flag[NCOLS * NMB];      // segment-done flags

__device__ __forceinline__ uint32_t s2u(const void* p) {
    uint32_t a;
    asm("{ .reg .u64 t; cvta.to.shared.u64 t, %1; cvt.u32.u64 %0, t; }" : "=r"(a) : "l"(p));
    return a;
}

__device__ __forceinline__ uint32_t h2u(__half2 h) {
    uint32_t u;
    memcpy(&u, &h, 4);
    return u;
}

// SW128-style swizzle for 128-byte rows (64 halves)
__device__ __forceinline__ uint32_t swz(uint32_t o) { return o ^ ((o >> 3) & 0x70); }

__device__ __forceinline__ void cpa16(uint32_t dst, const void* src) {
    asm volatile("cp.async.cg.shared.global [%0], [%1], 16;" :: "r"(dst), "l"(src) : "memory");
}
__device__ __forceinline__ void cpa_commit() {
    asm volatile("cp.async.commit_group;" ::: "memory");
}
__device__ __forceinline__ void cpa_wait1() {
    asm volatile("cp.async.wait_group 1;" ::: "memory");
}

__device__ __forceinline__ void ldm_x4(uint32_t* r, uint32_t addr) {
    asm volatile("ldmatrix.sync.aligned.m8n8.x4.shared.b16 {%0,%1,%2,%3}, [%4];"
                 : "=r"(r[0]), "=r"(r[1]), "=r"(r[2]), "=r"(r[3]) : "r"(addr));
}

__device__ __forceinline__ void mma_f16(float* d, const uint32_t* a, uint32_t b0, uint32_t b1) {
    asm volatile(
        "mma.sync.aligned.m16n8k16.row.col.f32.f16.f16.f32 "
        "{%0,%1,%2,%3}, {%4,%5,%6,%7}, {%8,%9}, {%0,%1,%2,%3};\n"
        : "+f"(d[0]), "+f"(d[1]), "+f"(d[2]), "+f"(d[3])
        : "r"(a[0]), "r"(a[1]), "r"(a[2]), "r"(a[3]), "r"(b0), "r"(b1));
}

__device__ __forceinline__ float sigmoidf_(float v) {
    return 1.0f / (1.0f + __expf(-v));
}

// ---- zero per-launch flags (graph replays re-run this) ----
__global__ void zero_flags_kernel()
{
    int i = blockIdx.x * blockDim.x + threadIdx.x;
    if (i < NCOLS * NMB) g_flag[i] = 0;
}

// ---- fp32 -> fp16 convert (x), streaming ----
__global__ void cvt_kernel(const float4* __restrict__ src, __half2* __restrict__ dst, int n4)
{
    int i = blockIdx.x * blockDim.x + threadIdx.x;
    if (i < n4) {
        float4 v = __ldcs(&src[i]);
        uint2 pk = make_uint2(h2u(__floats2half2_rn(v.x, v.y)),
                              h2u(__floats2half2_rn(v.z, v.w)));
        __stcs(reinterpret_cast<uint2*>(dst) + i, pk);
    }
}

// ---- fp32 -> fp16, interleaving W rows: dst row = 2*srcrow + parity ----
__global__ void cvt_w_kernel(const float4* __restrict__ src, int parity, int n4)
{
    int i = blockIdx.x * blockDim.x + threadIdx.x;
    if (i < n4) {
        float4 v = __ldcs(&src[i]);
        int row = i >> 7;              // DD/4 = 128 float4 per row
        int c4  = i & 127;
        uint2 pk = make_uint2(h2u(__floats2half2_rn(v.x, v.y)),
                              h2u(__floats2half2_rn(v.z, v.w)));
        uint2* dst = reinterpret_cast<uint2*>(g_wc) +
                     ((size_t)(2 * row + parity) * (DD / 4) + c4);
        __stcs(dst, pk);
    }
}

// ---- Fused GEMM + gate + carry-chained scan ----
// grid (256, 16): x = col + 32*b, y = seg (SLOWEST axis).
// Chain neighbors (seg, seg+1) are 256 bids apart (~one full wave), so a
// segment's carry is published ~a wave before its consumer's epilogue: spin~0.
// 256 threads (8 warps, 2x4), 2 CTAs/SM.
__global__ void __launch_bounds__(256, 2) fused_kernel(
    const float* __restrict__ ba, const float* __restrict__ bi,
    const float* __restrict__ gate, float* __restrict__ out)
{
    extern __shared__ char smem[];
    const uint32_t sbase = s2u(smem);

    const int tid  = threadIdx.x;
    const int wid  = tid >> 5;
    const int lane = tid & 31;
    const int wm   = wid >> 2;          // 0..1 -> 64-row slice
    const int wn   = wid & 3;           // 0..3 -> 32-col slice
    const int g    = lane >> 2;         // 0..7
    const int tg   = lane & 3;          // 0..3
    const int col  = blockIdx.x & 31;   // 0..31
    const int b    = blockIdx.x >> 5;   // 0..7
    const int seg  = blockIdx.y;        // 0..15
    const int mb   = b * NSEG + seg;    // 0..127
    const int m_blk = mb * CTA_M;
    const int n_blk = col * CTA_N;

    float acc[4][4][4];                 // [mt][nt][frag]
    #pragma unroll
    for (int mt = 0; mt < 4; mt++)
        #pragma unroll
        for (int nt = 0; nt < 4; nt++)
            #pragma unroll
            for (int r = 0; r < 4; r++) acc[mt][nt][r] = 0.f;

    // ---- base-register + immediate cp.async addressing ----
    const int r0 = tid >> 3, c0 = tid & 7;
    const uint32_t xs0 = sbase + swz(r0 * 128 + c0 * 16);
    const uint32_t ws0 = sbase + W_OFF + swz(r0 * 128 + c0 * 16);
    const __half* xg0 = g_xh + (size_t)(m_blk + r0) * DD + c0 * 8;
    const __half* wg0 = g_wc + (size_t)(n_blk + r0) * DD + c0 * 8;

    auto issue = [&](int kc, int slot) {   // kc, slot compile-time under unroll
        #pragma unroll
        for (int t = 0; t < 4; t++)
            cpa16(xs0 + slot * STAGE_BYTES + t * 4096,
                  xg0 + kc * TK + t * 32 * DD);
        #pragma unroll
        for (int t = 0; t < 4; t++)
            cpa16(ws0 + slot * STAGE_BYTES + t * 4096,
                  wg0 + kc * TK + t * 32 * DD);
        cpa_commit();
    };

    issue(0, 0); issue(1, 1);

    // Absolute swizzled ldsm offsets. swz(row*128 + kb), kb = kk*32 + acol:
    //   = row*128 + ((acol ^ ((row&7)<<4)) ^ kk*32)   (kk bits never carry)
    const int arow = lane & 15;
    const uint32_t acol = (lane >> 4) << 4;   // 0 or 16
    uint32_t aoff[4], boff[2];
    #pragma unroll
    for (int mt = 0; mt < 4; mt++) {
        int row = wm * 64 + mt * 16 + arow;
        aoff[mt] = sbase + row * 128 + (acol ^ ((row & 7) << 4));
    }
    #pragma unroll
    for (int bt = 0; bt < 2; bt++) {
        int row = wn * 32 + bt * 16 + arow;
        boff[bt] = sbase + W_OFF + row * 128 + (acol ^ ((row & 7) << 4));
    }

    #pragma unroll
    for (int kc = 0; kc < NCHUNK; kc++) {
        cpa_wait1();            // own group kc complete (kc+1 may be in flight)
        __syncthreads();        // ALL threads' waits done -> stage-kc data visible
        if (kc + 2 < NCHUNK) issue(kc + 2, (kc + 2) % STAGES);
        else cpa_commit();      // keep group counting uniform

        const uint32_t so = (kc % STAGES) * STAGE_BYTES;   // immediate under unroll

        // register double-buffered fragments
        uint32_t a[2][4][4], bw[2][2][4];
        #pragma unroll
        for (int mt = 0; mt < 4; mt++) ldm_x4(a[0][mt], aoff[mt] + so);
        #pragma unroll
        for (int bt = 0; bt < 2; bt++) ldm_x4(bw[0][bt], boff[bt] + so);

        #pragma unroll
        for (int kk = 0; kk < 4; kk++) {
            const int cur = kk & 1, nxt = cur ^ 1;
            if (kk < 3) {
                const uint32_t kx = (kk + 1) * 32;
                #pragma unroll
                for (int mt = 0; mt < 4; mt++) ldm_x4(a[nxt][mt], (aoff[mt] + so) ^ kx);
                #pragma unroll
                for (int bt = 0; bt < 2; bt++) ldm_x4(bw[nxt][bt], (boff[bt] + so) ^ kx);
            }
            #pragma unroll
            for (int mt = 0; mt < 4; mt++)
                #pragma unroll
                for (int nt = 0; nt < 4; nt++) {
                    const int bt = nt >> 1, sub = nt & 1;
                    mma_f16(acc[mt][nt], a[cur][mt], bw[cur][bt][sub], bw[cur][bt][sub + 2]);
                }
        }
    }

    // ---- epilogue 1: gate math -> smem tile of half2(alpha, drive) ----
    __syncthreads();   // all warps done with stage smem; safe to overwrite
    __half2* tile = reinterpret_cast<__half2*>(smem);   // [128][TILE_STRIDE]
    #pragma unroll
    for (int nt = 0; nt < 4; nt++) {
        const int ch = wn * 16 + nt * 4 + tg;             // 0..63
        const int i = col * 64 + ch;                      // global channel
        const float bav = __ldg(&ba[i]);
        const float biv = __ldg(&bi[i]);
        const float alv = sigmoidf_(__ldg(&gate[i]));
        #pragma unroll
        for (int mt = 0; mt < 4; mt++) {
            #pragma unroll
            for (int half = 0; half < 2; half++) {
                const int ml = wm * 64 + mt * 16 + g + half * 8;   // 0..127
                float pa = acc[mt][nt][2 * half]     + bav;
                float pi = acc[mt][nt][2 * half + 1] + biv;
                float rg = sigmoidf_(pa);
                float ig = sigmoidf_(pi);
                float aa = alv * __expf(-LN3 * rg);
                float dr = sqrtf(fmaxf(1.0f - aa * aa, 0.0f)) * (ig * pi);
                tile[ml * TILE_STRIDE + ch] = __floats2half2_rn(aa, dr);
            }
        }
    }
    __syncthreads();

    // ---- epilogue 2: carry-chained scan over this CTA's 128 s-steps ----
    if (tid < 64) {
        const int i = col * 64 + tid;
        float h = 0.0f;
        if (seg) {
            volatile int* fp = &g_flag[col * NMB + mb - 1];
            while (*fp == 0) { }
            __threadfence();
            h = g_carry[(size_t)i * BB + b];
        }
        float* op = out + ((size_t)b * SS + seg * 128) * II + i;
        #pragma unroll 4
        for (int s = 0; s < 128; s++) {
            float2 p = __half22float2(tile[s * TILE_STRIDE + tid]);
            h = fmaf(p.x, h, p.y);
            __stcs(&op[(size_t)s * II], h);
        }
        if (seg != NSEG - 1) g_carry[(size_t)i * BB + b] = h;
    }
    __syncthreads();               // all 64 carries written
    if (tid == 0 && seg != NSEG - 1) {
        __threadfence();           // carries visible before flag
        atomicExch(&g_flag[col * NMB + mb], 1);
    }
}

extern "C" void kernel_launch(void* const* d_in, const int* in_sizes, int n_in,
                              void* d_out, int out_size)
{
    const float* x    = (const float*)d_in[0];
    const float* Wa   = (const float*)d_in[1];
    const float* ba   = (const float*)d_in[2];
    const float* Wi   = (const float*)d_in[3];
    const float* bi   = (const float*)d_in[4];
    const float* gate = (const float*)d_in[5];
    float* out = (float*)d_out;

    __half* xh; cudaGetSymbolAddress((void**)&xh, g_xh);

    zero_flags_kernel<<<(NCOLS * NMB + 255) / 256, 256>>>();

    const int nx4 = MM * DD / 4;
    const int nw4 = II * DD / 4;
    cvt_kernel<<<(nx4 + 255) / 256, 256>>>((const float4*)x, (__half2*)xh, nx4);
    cvt_w_kernel<<<(nw4 + 255) / 256, 256>>>((const float4*)Wa, 0, nw4);
    cvt_w_kernel<<<(nw4 + 255) / 256, 256>>>((const float4*)Wi, 1, nw4);

    cudaFuncSetAttribute(fused_kernel,
                         cudaFuncAttributeMaxDynamicSharedMemorySize,
                         STAGES * STAGE_BYTES);
    dim3 grid(NCOLS * BB, NSEG);   // (256, 16): seg slow -> carry ready a wave early
    fused_kernel<<<grid, 256, STAGES * STAGE_BYTES>>>(ba, bi, gate, out);
}

// round 17
// speedup vs baseline: 1.4204x; 1.0246x over previous
#include <cuda_runtime.h>
#include <cuda_fp16.h>
#include <cstdint>

// Problem dims (fixed per reference setup_inputs)
#define BB 8
#define SS 2048
#define DD 512
#define II 2048
#define MM (BB*SS)   // 16384 rows (b*S+s)
#define NN (2*II)    // 4096 interleaved output cols (even=pa, odd=pi)

#define LN3 1.0986122886681098f

// GEMM tiling
#define CTA_M 128
#define CTA_N 128          // = 64 channels
#define TK 64              // K halves per chunk (128B rows)
#define NCHUNK (DD/TK)     // 8
#define STAGES 3
#define STAGE_BYTES 32768  // x 16K + Wcat 16K
#define W_OFF 16384

#define NCOLS (NN / CTA_N)     // 32
#define NMB   (MM / CTA_M)     // 128
#define NSEG  16               // segments per batch chain
#define TILE_STRIDE 68         // half2 per row: bank=(4*ml+ch)%32 -> conflict-free

// prep kernel partition
#define NX4 (MM * DD / 4)          // 2,097,152 float4 of x
#define NW4 (II * DD / 4)          //   262,144 float4 per W
#define NFLAG (NCOLS * NMB)        // 4096
#define PREP_TOTAL (NX4 + 2 * NW4 + NFLAG)

// Scratch
__device__ __half g_xh[(size_t)MM * DD];    // [m, k]
__device__ __half g_wc[(size_t)NN * DD];    // interleaved [2i+p, k]
__device__ float  g_carry[(size_t)II * BB]; // h carry per (channel, b)
__device__ int    g_flag[NCOLS * NMB];      // segment-done flags

__device__ __forceinline__ uint32_t s2u(const void* p) {
    uint32_t a;
    asm("{ .reg .u64 t; cvta.to.shared.u64 t, %1; cvt.u32.u64 %0, t; }" : "=r"(a) : "l"(p));
    return a;
}

__device__ __forceinline__ uint32_t h2u(__half2 h) {
    uint32_t u;
    memcpy(&u, &h, 4);
    return u;
}

// SW128-style swizzle for 128-byte rows (64 halves)
__device__ __forceinline__ uint32_t swz(uint32_t o) { return o ^ ((o >> 3) & 0x70); }

__device__ __forceinline__ void cpa16(uint32_t dst, const void* src) {
    asm volatile("cp.async.cg.shared.global [%0], [%1], 16;" :: "r"(dst), "l"(src) : "memory");
}
__device__ __forceinline__ void cpa_commit() {
    asm volatile("cp.async.commit_group;" ::: "memory");
}
__device__ __forceinline__ void cpa_wait1() {
    asm volatile("cp.async.wait_group 1;" ::: "memory");
}

__device__ __forceinline__ void ldm_x4(uint32_t* r, uint32_t addr) {
    asm volatile("ldmatrix.sync.aligned.m8n8.x4.shared.b16 {%0,%1,%2,%3}, [%4];"
                 : "=r"(r[0]), "=r"(r[1]), "=r"(r[2]), "=r"(r[3]) : "r"(addr));
}

__device__ __forceinline__ void mma_f16(float* d, const uint32_t* a, uint32_t b0, uint32_t b1) {
    asm volatile(
        "mma.sync.aligned.m16n8k16.row.col.f32.f16.f16.f32 "
        "{%0,%1,%2,%3}, {%4,%5,%6,%7}, {%8,%9}, {%0,%1,%2,%3};\n"
        : "+f"(d[0]), "+f"(d[1]), "+f"(d[2]), "+f"(d[3])
        : "r"(a[0]), "r"(a[1]), "r"(a[2]), "r"(a[3]), "r"(b0), "r"(b1));
}

__device__ __forceinline__ float sigmoidf_(float v) {
    return 1.0f / (1.0f + __expf(-v));
}

// ---- merged prep: cvt x, cvt+interleave Wa/Wi, zero flags (one launch) ----
__global__ void prep_kernel(const float4* __restrict__ x,
                            const float4* __restrict__ Wa,
                            const float4* __restrict__ Wi)
{
    int idx = blockIdx.x * blockDim.x + threadIdx.x;
    if (idx < NX4) {
        float4 v = __ldcs(&x[idx]);
        uint2 pk = make_uint2(h2u(__floats2half2_rn(v.x, v.y)),
                              h2u(__floats2half2_rn(v.z, v.w)));
        __stcs(reinterpret_cast<uint2*>(g_xh) + idx, pk);
    } else if (idx < NX4 + 2 * NW4) {
        int w = idx - NX4;
        int parity = (w >= NW4) ? 1 : 0;
        int i = parity ? w - NW4 : w;
        float4 v = __ldcs(parity ? &Wi[i] : &Wa[i]);
        int row = i >> 7;              // DD/4 = 128 float4 per row
        int c4  = i & 127;
        uint2 pk = make_uint2(h2u(__floats2half2_rn(v.x, v.y)),
                              h2u(__floats2half2_rn(v.z, v.w)));
        uint2* dst = reinterpret_cast<uint2*>(g_wc) +
                     ((size_t)(2 * row + parity) * (DD / 4) + c4);
        __stcs(dst, pk);
    } else if (idx < PREP_TOTAL) {
        g_flag[idx - NX4 - 2 * NW4] = 0;
    }
}

// ---- Fused GEMM + gate + carry-chained scan ----
// grid (256, 16): x = col + 32*b, y = seg (SLOWEST axis).
// Chain neighbors (seg, seg+1) are 256 bids apart (~one full wave), so a
// segment's carry is published ~a wave before its consumer's epilogue: spin~0.
// 256 threads (8 warps, 2x4), 2 CTAs/SM.
__global__ void __launch_bounds__(256, 2) fused_kernel(
    const float* __restrict__ ba, const float* __restrict__ bi,
    const float* __restrict__ gate, float* __restrict__ out)
{
    extern __shared__ char smem[];
    const uint32_t sbase = s2u(smem);

    const int tid  = threadIdx.x;
    const int wid  = tid >> 5;
    const int lane = tid & 31;
    const int wm   = wid >> 2;          // 0..1 -> 64-row slice
    const int wn   = wid & 3;           // 0..3 -> 32-col slice
    const int g    = lane >> 2;         // 0..7
    const int tg   = lane & 3;          // 0..3
    const int col  = blockIdx.x & 31;   // 0..31
    const int b    = blockIdx.x >> 5;   // 0..7
    const int seg  = blockIdx.y;        // 0..15
    const int mb   = b * NSEG + seg;    // 0..127
    const int m_blk = mb * CTA_M;
    const int n_blk = col * CTA_N;

    float acc[4][4][4];                 // [mt][nt][frag]
    #pragma unroll
    for (int mt = 0; mt < 4; mt++)
        #pragma unroll
        for (int nt = 0; nt < 4; nt++)
            #pragma unroll
            for (int r = 0; r < 4; r++) acc[mt][nt][r] = 0.f;

    // ---- base-register + immediate cp.async addressing ----
    const int r0 = tid >> 3, c0 = tid & 7;
    const uint32_t xs0 = sbase + swz(r0 * 128 + c0 * 16);
    const uint32_t ws0 = sbase + W_OFF + swz(r0 * 128 + c0 * 16);
    const __half* xg0 = g_xh + (size_t)(m_blk + r0) * DD + c0 * 8;
    const __half* wg0 = g_wc + (size_t)(n_blk + r0) * DD + c0 * 8;

    auto issue = [&](int kc, int slot) {   // kc, slot compile-time under unroll
        #pragma unroll
        for (int t = 0; t < 4; t++)
            cpa16(xs0 + slot * STAGE_BYTES + t * 4096,
                  xg0 + kc * TK + t * 32 * DD);
        #pragma unroll
        for (int t = 0; t < 4; t++)
            cpa16(ws0 + slot * STAGE_BYTES + t * 4096,
                  wg0 + kc * TK + t * 32 * DD);
        cpa_commit();
    };

    issue(0, 0); issue(1, 1);

    // Absolute swizzled ldsm offsets. swz(row*128 + kb), kb = kk*32 + acol:
    //   = row*128 + ((acol ^ ((row&7)<<4)) ^ kk*32)   (kk bits never carry)
    const int arow = lane & 15;
    const uint32_t acol = (lane >> 4) << 4;   // 0 or 16
    uint32_t aoff[4], boff[2];
    #pragma unroll
    for (int mt = 0; mt < 4; mt++) {
        int row = wm * 64 + mt * 16 + arow;
        aoff[mt] = sbase + row * 128 + (acol ^ ((row & 7) << 4));
    }
    #pragma unroll
    for (int bt = 0; bt < 2; bt++) {
        int row = wn * 32 + bt * 16 + arow;
        boff[bt] = sbase + W_OFF + row * 128 + (acol ^ ((row & 7) << 4));
    }

    #pragma unroll
    for (int kc = 0; kc < NCHUNK; kc++) {
        cpa_wait1();            // own group kc complete (kc+1 may be in flight)
        __syncthreads();        // ALL threads' waits done -> stage-kc data visible
        if (kc + 2 < NCHUNK) issue(kc + 2, (kc + 2) % STAGES);
        else cpa_commit();      // keep group counting uniform

        const uint32_t so = (kc % STAGES) * STAGE_BYTES;   // immediate under unroll

        // register double-buffered fragments
        uint32_t a[2][4][4], bw[2][2][4];
        #pragma unroll
        for (int mt = 0; mt < 4; mt++) ldm_x4(a[0][mt], aoff[mt] + so);
        #pragma unroll
        for (int bt = 0; bt < 2; bt++) ldm_x4(bw[0][bt], boff[bt] + so);

        #pragma unroll
        for (int kk = 0; kk < 4; kk++) {
            const int cur = kk & 1, nxt = cur ^ 1;
            if (kk < 3) {
                const uint32_t kx = (kk + 1) * 32;
                #pragma unroll
                for (int mt = 0; mt < 4; mt++) ldm_x4(a[nxt][mt], (aoff[mt] + so) ^ kx);
                #pragma unroll
                for (int bt = 0; bt < 2; bt++) ldm_x4(bw[nxt][bt], (boff[bt] + so) ^ kx);
            }
            #pragma unroll
            for (int mt = 0; mt < 4; mt++)
                #pragma unroll
                for (int nt = 0; nt < 4; nt++) {
                    const int bt = nt >> 1, sub = nt & 1;
                    mma_f16(acc[mt][nt], a[cur][mt], bw[cur][bt][sub], bw[cur][bt][sub + 2]);
                }
        }
    }

    // ---- epilogue 1: gate math -> smem tile of half2(alpha, drive) ----
    __syncthreads();   // all warps done with stage smem; safe to overwrite
    __half2* tile = reinterpret_cast<__half2*>(smem);   // [128][TILE_STRIDE]
    #pragma unroll
    for (int nt = 0; nt < 4; nt++) {
        const int ch = wn * 16 + nt * 4 + tg;             // 0..63
        const int i = col * 64 + ch;                      // global channel
        const float bav = __ldg(&ba[i]);
        const float biv = __ldg(&bi[i]);
        const float alv = sigmoidf_(__ldg(&gate[i]));
        #pragma unroll
        for (int mt = 0; mt < 4; mt++) {
            #pragma unroll
            for (int half = 0; half < 2; half++) {
                const int ml = wm * 64 + mt * 16 + g + half * 8;   // 0..127
                float pa = acc[mt][nt][2 * half]     + bav;
                float pi = acc[mt][nt][2 * half + 1] + biv;
                float rg = sigmoidf_(pa);
                float ig = sigmoidf_(pi);
                float aa = alv * __expf(-LN3 * rg);
                float dr = sqrtf(fmaxf(1.0f - aa * aa, 0.0f)) * (ig * pi);
                tile[ml * TILE_STRIDE + ch] = __floats2half2_rn(aa, dr);
            }
        }
    }
    __syncthreads();

    // ---- epilogue 2: carry-chained scan over this CTA's 128 s-steps ----
    if (tid < 64) {
        const int i = col * 64 + tid;
        float h = 0.0f;
        if (seg) {
            volatile int* fp = &g_flag[col * NMB + mb - 1];
            while (*fp == 0) { }
            __threadfence();
            h = g_carry[(size_t)i * BB + b];
        }
        float* op = out + ((size_t)b * SS + seg * 128) * II + i;
        #pragma unroll 4
        for (int s = 0; s < 128; s++) {
            float2 p = __half22float2(tile[s * TILE_STRIDE + tid]);
            h = fmaf(p.x, h, p.y);
            __stcs(&op[(size_t)s * II], h);
        }
        if (seg != NSEG - 1) g_carry[(size_t)i * BB + b] = h;
    }
    __syncthreads();               // all 64 carries written
    if (tid == 0 && seg != NSEG - 1) {
        __threadfence();           // carries visible before flag
        atomicExch(&g_flag[col * NMB + mb], 1);
    }
}

extern "C" void kernel_launch(void* const* d_in, const int* in_sizes, int n_in,
                              void* d_out, int out_size)
{
    const float* x    = (const float*)d_in[0];
    const float* Wa   = (const float*)d_in[1];
    const float* ba   = (const float*)d_in[2];
    const float* Wi   = (const float*)d_in[3];
    const float* bi   = (const float*)d_in[4];
    const float* gate = (const float*)d_in[5];
    float* out = (float*)d_out;

    prep_kernel<<<(PREP_TOTAL + 255) / 256, 256>>>(
        (const float4*)x, (const float4*)Wa, (const float4*)Wi);

    cudaFuncSetAttribute(fused_kernel,
                         cudaFuncAttributeMaxDynamicSharedMemorySize,
                         STAGES * STAGE_BYTES);
    dim3 grid(NCOLS * BB, NSEG);   // (256, 16): seg slow -> carry ready a wave early
    fused_kernel<<<grid, 256, STAGES * STAGE_BYTES>>>(ba, bi, gate, out);
}